// round 7
// baseline (speedup 1.0000x reference)
#include <cuda_runtime.h>
#include <cuda_fp16.h>
#include <cstdint>

// ===========================================================================
// TernaryLinear: out[8192,11008] = x[8192,4096] @ sign(W)[11008,4096]^T + bias
//
// fp16 x, fp16 sign(W), mma.sync.m16n8k16.f32, cp.async 3-stage pipeline with
// BK=64 (4 k-steps per stage, half the barriers of R4), XOR-swizzled 128B
// rows (conflict-free ldsm + cp writes), frag double-buffering across stage
// boundaries, L2-friendly raster. CTA 128x256, 8 warps, warp 64x64.
// R7: resubmit of R5/R6 (both were broker-side container failures; the R0
// stub failed identically, so failures are kernel-independent).
// ===========================================================================

#define DEVFN __device__ __forceinline__

static constexpr int Mdim = 8192, Ndim = 11008, Kdim = 4096;
static constexpr int BM = 128, BN = 256;
static constexpr int ROWB = 128;                   // 64 fp16 = 128 B per row
static constexpr int NSTAGES = 3;
static constexpr int A_BYTES = BM * ROWB;          // 16384
static constexpr int B_BYTES = BN * ROWB;          // 32768
static constexpr int STAGE = A_BYTES + B_BYTES;    // 49152
static constexpr int SMEM_TOTAL = NSTAGES * STAGE; // 147456
static constexpr int KITERS = Kdim / 64;           // 64 BK=64 stages

static constexpr int MTILES = Mdim / BM;           // 64
static constexpr int NTILES = Ndim / BN;           // 43
static constexpr int GROUP_M = 16;

// XOR swizzle on 16B columns within a 128B row: col16' = col16 ^ (row & 7)
DEVFN uint32_t swz(uint32_t row, uint32_t col16) {
    return row * ROWB + ((col16 ^ (row & 7u)) << 4);
}

// -------------------- scratch (device globals; no cudaMalloc) --------------
__device__ __align__(128) unsigned char g_xh[(size_t)Mdim * Kdim * 2];
__device__ __align__(128) unsigned char g_wh[(size_t)Ndim * Kdim * 2];

// -------------------- PTX helpers ------------------------------------------
DEVFN uint32_t smem_u32(const void* p) {
    uint32_t a;
    asm("{ .reg .u64 t; cvta.to.shared.u64 t, %1; cvt.u32.u64 %0, t; }"
        : "=r"(a) : "l"(p));
    return a;
}
DEVFN void cp16(uint32_t dst, const void* src) {
    asm volatile("cp.async.cg.shared.global [%0], [%1], 16;"
                 :: "r"(dst), "l"(src) : "memory");
}
DEVFN void cp_commit() { asm volatile("cp.async.commit_group;" ::: "memory"); }
template <int N> DEVFN void cp_wait() {
    asm volatile("cp.async.wait_group %0;" :: "n"(N) : "memory");
}
DEVFN void ldsm4(uint32_t* r, uint32_t addr) {
    asm volatile("ldmatrix.sync.aligned.m8n8.x4.shared.b16 {%0,%1,%2,%3}, [%4];"
                 : "=r"(r[0]), "=r"(r[1]), "=r"(r[2]), "=r"(r[3]) : "r"(addr));
}
DEVFN void mma16816(float* d, const uint32_t* a, uint32_t b0, uint32_t b1) {
    asm volatile(
        "mma.sync.aligned.m16n8k16.row.col.f32.f16.f16.f32 "
        "{%0,%1,%2,%3}, {%4,%5,%6,%7}, {%8,%9}, {%0,%1,%2,%3};"
        : "+f"(d[0]), "+f"(d[1]), "+f"(d[2]), "+f"(d[3])
        : "r"(a[0]), "r"(a[1]), "r"(a[2]), "r"(a[3]), "r"(b0), "r"(b1));
}

// -------------------- fused preprocessing ----------------------------------
static constexpr int XBLK = (Mdim * Kdim / 4) / 256;   // 32768
static constexpr int WBLK = (Ndim * Kdim / 4) / 256;   // 44032

__global__ void prep_fused(const float4* __restrict__ x,
                           const float4* __restrict__ w,
                           uint2* __restrict__ xh, uint2* __restrict__ wh) {
    int b = blockIdx.x;
    if (b < XBLK) {
        int i = b * 256 + threadIdx.x;
        float4 v = x[i];
        __half2 h0 = __floats2half2_rn(v.x, v.y);
        __half2 h1 = __floats2half2_rn(v.z, v.w);
        uint2 u;
        u.x = *reinterpret_cast<uint32_t*>(&h0);
        u.y = *reinterpret_cast<uint32_t*>(&h1);
        xh[i] = u;
    } else {
        int i = (b - XBLK) * 256 + threadIdx.x;
        float4 v = w[i];
        float f[4] = {v.x, v.y, v.z, v.w};
        uint32_t s[4];
#pragma unroll
        for (int j = 0; j < 4; ++j)
            s[j] = f[j] > 0.f ? 0x3C00u : (f[j] < 0.f ? 0xBC00u : 0u);
        uint2 u;
        u.x = s[0] | (s[1] << 16);
        u.y = s[2] | (s[3] << 16);
        wh[i] = u;
    }
}

// -------------------- GEMM kernel ------------------------------------------
__global__ void __launch_bounds__(256, 1) gemm_f16(
    const unsigned char* __restrict__ A,   // fp16 [M][K]
    const unsigned char* __restrict__ B,   // fp16 [N][K]
    const float* __restrict__ bias,
    float* __restrict__ out)
{
    extern __shared__ __align__(128) unsigned char smem[];
    const uint32_t sbase = smem_u32(smem);
    const int tid = threadIdx.x;
    const int lane = tid & 31;
    const int wid = tid >> 5;
    const int wm = wid >> 2;
    const int wn = wid & 3;

    // ---- raster: bands of GROUP_M M-tiles sweeping N (L2 reuse) ----
    const int bid = blockIdx.y * gridDim.x + blockIdx.x;
    const int band = bid / (GROUP_M * NTILES);
    const int rem = bid % (GROUP_M * NTILES);
    const int m0 = (band * GROUP_M + (rem % GROUP_M)) * BM;
    const int n0 = (rem / GROUP_M) * BN;

    // ---- cp.async addressing: thread -> (row = tid/2, half = tid&1) ----
    const int crow = tid >> 1;            // 0..127
    const int chalf = tid & 1;            // 64B half of 128B row
    const size_t rowbytes = (size_t)Kdim * 2;
    const unsigned char* gA = A + (size_t)(m0 + crow) * rowbytes + chalf * 64;
    const unsigned char* gB0 = B + (size_t)(n0 + crow) * rowbytes + chalf * 64;
    const unsigned char* gB1 = gB0 + 128 * rowbytes;
    // swizzled smem column bases for the 4 chunks this thread writes
    uint32_t sAo[4], sB0o[4], sB1o[4];
#pragma unroll
    for (int j = 0; j < 4; ++j) {
        uint32_t c = chalf * 4 + j;
        sAo[j] = swz(crow, c);
        sB0o[j] = A_BYTES + swz(crow, c);
        sB1o[j] = A_BYTES + swz(crow + 128, c);
    }

    auto load_stage = [&](int it, int s) {
        const uint32_t so = sbase + (uint32_t)s * STAGE;
        const size_t ko = (size_t)it * 128;
#pragma unroll
        for (int j = 0; j < 4; ++j) {
            cp16(so + sAo[j], gA + ko + j * 16);
            cp16(so + sB0o[j], gB0 + ko + j * 16);
            cp16(so + sB1o[j], gB1 + ko + j * 16);
        }
    };

    // ---- ldmatrix per-lane swizzled addresses ----
    const int arow = wm * 64 + (lane & 15);
    const uint32_t acb = (lane & 16) >> 4;             // col16 bit
    const int brow = wn * 64 + ((lane >> 4) << 3) + (lane & 7);
    const uint32_t bcb = (lane & 8) >> 3;
    uint32_t aoff[4][4], boff[4][4];
#pragma unroll
    for (int f = 0; f < 4; ++f)
#pragma unroll
        for (int ks = 0; ks < 4; ++ks) {
            aoff[f][ks] = swz(arow + f * 16, ks * 2 + acb);
            boff[f][ks] = A_BYTES + swz(brow + f * 16, ks * 2 + bcb);
        }

    float acc[4][8][4];
#pragma unroll
    for (int i = 0; i < 4; ++i)
#pragma unroll
        for (int j = 0; j < 8; ++j)
#pragma unroll
            for (int k = 0; k < 4; ++k) acc[i][j][k] = 0.f;

    // ---- prologue ----
    load_stage(0, 0); cp_commit();
    load_stage(1, 1); cp_commit();
    cp_wait<1>();                 // stage 0 resident
    __syncthreads();

    uint32_t afr[2][4][4], bfr[2][4][4];
    {
        const uint32_t s0 = sbase;
#pragma unroll
        for (int f = 0; f < 4; ++f) ldsm4(afr[0][f], s0 + aoff[f][0]);
#pragma unroll
        for (int p = 0; p < 4; ++p) ldsm4(bfr[0][p], s0 + boff[p][0]);
    }

    int cur = 0;
    for (int i = 0; i < KITERS; ++i) {
        // issue stage i+2 into slot (i+2)%3 (slot of stage i-1; all warps
        // passed end-of-iter-(i-1) barrier after their last read of it)
        if (i + 2 < KITERS) load_stage(i + 2, (i + 2) % NSTAGES);
        cp_commit();

        const uint32_t so = sbase + (uint32_t)(i % NSTAGES) * STAGE;
        // ks0..ks2: prefetch next k-step frags, then mma
#pragma unroll
        for (int ks = 0; ks < 3; ++ks) {
#pragma unroll
            for (int f = 0; f < 4; ++f) ldsm4(afr[cur ^ 1][f], so + aoff[f][ks + 1]);
#pragma unroll
            for (int p = 0; p < 4; ++p) ldsm4(bfr[cur ^ 1][p], so + boff[p][ks + 1]);
#pragma unroll
            for (int f = 0; f < 4; ++f)
#pragma unroll
                for (int p = 0; p < 4; ++p) {
                    mma16816(acc[f][2 * p], afr[cur][f], bfr[cur][p][0], bfr[cur][p][1]);
                    mma16816(acc[f][2 * p + 1], afr[cur][f], bfr[cur][p][2], bfr[cur][p][3]);
                }
            cur ^= 1;
        }
        // ks3: mma only
#pragma unroll
        for (int f = 0; f < 4; ++f)
#pragma unroll
            for (int p = 0; p < 4; ++p) {
                mma16816(acc[f][2 * p], afr[cur][f], bfr[cur][p][0], bfr[cur][p][1]);
                mma16816(acc[f][2 * p + 1], afr[cur][f], bfr[cur][p][2], bfr[cur][p][3]);
            }

        // groups committed: s0..s(i+2); wait<1> -> s(i+1) resident
        cp_wait<1>();
        __syncthreads();

        // prefetch k0 frags of stage i+1
        if (i + 1 < KITERS) {
            const uint32_t sn = sbase + (uint32_t)((i + 1) % NSTAGES) * STAGE;
#pragma unroll
            for (int f = 0; f < 4; ++f) ldsm4(afr[cur ^ 1][f], sn + aoff[f][0]);
#pragma unroll
            for (int p = 0; p < 4; ++p) ldsm4(bfr[cur ^ 1][p], sn + boff[p][0]);
            cur ^= 1;
        }
    }

    // ---- epilogue: +bias, write float2 ----
    const int r0 = m0 + wm * 64 + (lane >> 2);
    const int c0 = n0 + wn * 64 + (lane & 3) * 2;
#pragma unroll
    for (int f = 0; f < 4; ++f) {
#pragma unroll
        for (int g = 0; g < 8; ++g) {
            int row = r0 + f * 16;
            int col = c0 + g * 8;
            float2 bz = *reinterpret_cast<const float2*>(bias + col);
            float2 o01, o23;
            o01.x = acc[f][g][0] + bz.x;
            o01.y = acc[f][g][1] + bz.y;
            o23.x = acc[f][g][2] + bz.x;
            o23.y = acc[f][g][3] + bz.y;
            *reinterpret_cast<float2*>(out + (size_t)row * Ndim + col) = o01;
            *reinterpret_cast<float2*>(out + (size_t)(row + 8) * Ndim + col) = o23;
        }
    }
}

// -------------------- host side --------------------------------------------
extern "C" void kernel_launch(void* const* d_in, const int* in_sizes, int n_in,
                              void* d_out, int out_size) {
    const float* x = (const float*)d_in[0];
    const float* w = (const float*)d_in[1];
    const float* bias = (const float*)d_in[2];
    float* out = (float*)d_out;

    void *p_xh = nullptr, *p_wh = nullptr;
    cudaGetSymbolAddress(&p_xh, g_xh);
    cudaGetSymbolAddress(&p_wh, g_wh);

    prep_fused<<<XBLK + WBLK, 256>>>((const float4*)x, (const float4*)w,
                                     (uint2*)p_xh, (uint2*)p_wh);

    static bool attr_set = false;
    if (!attr_set) {
        cudaFuncSetAttribute(gemm_f16,
                             cudaFuncAttributeMaxDynamicSharedMemorySize,
                             SMEM_TOTAL);
        attr_set = true;
    }

    dim3 grid(NTILES, MTILES);   // 2752 CTAs, rasterized in-kernel
    gemm_f16<<<grid, 256, SMEM_TOTAL>>>(
        (const unsigned char*)p_xh, (const unsigned char*)p_wh, bias, out);
}

// round 8
// speedup vs baseline: 1.0500x; 1.0500x over previous
#include <cuda_runtime.h>
#include <cuda_fp16.h>
#include <cstdint>

// ===========================================================================
// TernaryLinear: out[8192,11008] = x[8192,4096] @ sign(W)[11008,4096]^T + bias
//
// fp16 x, fp16 sign(W), mma.sync.m16n8k16.f32, cp.async 3-stage pipeline,
// BK=64 (4 k-steps/stage), XOR-swizzled 128B rows. R8: spill-free addressing —
// all swizzled smem addresses derived from 8 base regs via XOR (16≡0 mod 8
// keeps the swizzle phase constant across fragments), fixing R7's
// local-memory spills (32 addr regs -> L1tex 84.7%, tensor 30%).
// CTA 128x256, 8 warps, warp 64x64, L2-friendly raster.
// ===========================================================================

#define DEVFN __device__ __forceinline__

static constexpr int Mdim = 8192, Ndim = 11008, Kdim = 4096;
static constexpr int BM = 128, BN = 256;
static constexpr int ROWB = 128;                   // 64 fp16 = 128 B per row
static constexpr int NSTAGES = 3;
static constexpr int A_BYTES = BM * ROWB;          // 16384
static constexpr int B_BYTES = BN * ROWB;          // 32768
static constexpr int STAGE = A_BYTES + B_BYTES;    // 49152
static constexpr int SMEM_TOTAL = NSTAGES * STAGE; // 147456
static constexpr int KITERS = Kdim / 64;           // 64 BK=64 stages

static constexpr int MTILES = Mdim / BM;           // 64
static constexpr int NTILES = Ndim / BN;           // 43
static constexpr int GROUP_M = 16;

// XOR swizzle on 16B columns within a 128B row: col16' = col16 ^ (row & 7)
DEVFN uint32_t swz(uint32_t row, uint32_t col16) {
    return row * ROWB + ((col16 ^ (row & 7u)) << 4);
}

// -------------------- scratch (device globals; no cudaMalloc) --------------
__device__ __align__(128) unsigned char g_xh[(size_t)Mdim * Kdim * 2];
__device__ __align__(128) unsigned char g_wh[(size_t)Ndim * Kdim * 2];

// -------------------- PTX helpers ------------------------------------------
DEVFN uint32_t smem_u32(const void* p) {
    uint32_t a;
    asm("{ .reg .u64 t; cvta.to.shared.u64 t, %1; cvt.u32.u64 %0, t; }"
        : "=r"(a) : "l"(p));
    return a;
}
DEVFN void cp16(uint32_t dst, const void* src) {
    asm volatile("cp.async.cg.shared.global [%0], [%1], 16;"
                 :: "r"(dst), "l"(src) : "memory");
}
DEVFN void cp_commit() { asm volatile("cp.async.commit_group;" ::: "memory"); }
template <int N> DEVFN void cp_wait() {
    asm volatile("cp.async.wait_group %0;" :: "n"(N) : "memory");
}
DEVFN void ldsm4(uint32_t* r, uint32_t addr) {
    asm volatile("ldmatrix.sync.aligned.m8n8.x4.shared.b16 {%0,%1,%2,%3}, [%4];"
                 : "=r"(r[0]), "=r"(r[1]), "=r"(r[2]), "=r"(r[3]) : "r"(addr));
}
DEVFN void mma16816(float* d, const uint32_t* a, uint32_t b0, uint32_t b1) {
    asm volatile(
        "mma.sync.aligned.m16n8k16.row.col.f32.f16.f16.f32 "
        "{%0,%1,%2,%3}, {%4,%5,%6,%7}, {%8,%9}, {%0,%1,%2,%3};"
        : "+f"(d[0]), "+f"(d[1]), "+f"(d[2]), "+f"(d[3])
        : "r"(a[0]), "r"(a[1]), "r"(a[2]), "r"(a[3]), "r"(b0), "r"(b1));
}

// -------------------- fused preprocessing ----------------------------------
static constexpr int XBLK = (Mdim * Kdim / 4) / 256;   // 32768
static constexpr int WBLK = (Ndim * Kdim / 4) / 256;   // 44032

__global__ void prep_fused(const float4* __restrict__ x,
                           const float4* __restrict__ w,
                           uint2* __restrict__ xh, uint2* __restrict__ wh) {
    int b = blockIdx.x;
    if (b < XBLK) {
        int i = b * 256 + threadIdx.x;
        float4 v = x[i];
        __half2 h0 = __floats2half2_rn(v.x, v.y);
        __half2 h1 = __floats2half2_rn(v.z, v.w);
        uint2 u;
        u.x = *reinterpret_cast<uint32_t*>(&h0);
        u.y = *reinterpret_cast<uint32_t*>(&h1);
        xh[i] = u;
    } else {
        int i = (b - XBLK) * 256 + threadIdx.x;
        float4 v = w[i];
        float f[4] = {v.x, v.y, v.z, v.w};
        uint32_t s[4];
#pragma unroll
        for (int j = 0; j < 4; ++j)
            s[j] = f[j] > 0.f ? 0x3C00u : (f[j] < 0.f ? 0xBC00u : 0u);
        uint2 u;
        u.x = s[0] | (s[1] << 16);
        u.y = s[2] | (s[3] << 16);
        wh[i] = u;
    }
}

// -------------------- GEMM kernel ------------------------------------------
__global__ void __launch_bounds__(256, 1) gemm_f16(
    const unsigned char* __restrict__ A,   // fp16 [M][K]
    const unsigned char* __restrict__ B,   // fp16 [N][K]
    const float* __restrict__ bias,
    float* __restrict__ out)
{
    extern __shared__ __align__(128) unsigned char smem[];
    const uint32_t sbase = smem_u32(smem);
    const int tid = threadIdx.x;
    const int lane = tid & 31;
    const int wid = tid >> 5;
    const int wm = wid >> 2;
    const int wn = wid & 3;

    // ---- raster: bands of GROUP_M M-tiles sweeping N (L2 reuse) ----
    const int bid = blockIdx.y * gridDim.x + blockIdx.x;
    const int band = bid / (GROUP_M * NTILES);
    const int rem = bid % (GROUP_M * NTILES);
    const int m0 = (band * GROUP_M + (rem % GROUP_M)) * BM;
    const int n0 = (rem / GROUP_M) * BN;

    // ---- cp.async addressing: ONE relative smem offset, rest derived ----
    const int crow = tid >> 1;            // 0..127
    const int chalf = tid & 1;            // 64B half of 128B row
    const size_t rowbytes = (size_t)Kdim * 2;                    // 8192
    const unsigned char* gA = A + (size_t)(m0 + crow) * rowbytes + chalf * 64;
    const unsigned char* gB = B + (size_t)(n0 + crow) * rowbytes + chalf * 64;
    const uint32_t rA = swz(crow, chalf * 4);   // chunk j: rA ^ (j<<4)
    // B rows 128..255 live at +A_BYTES+16384 ((crow+128)&7 == crow&7)

    auto load_stage = [&](int it, int s) {
        const uint32_t so = sbase + (uint32_t)s * STAGE;
        const size_t ko = (size_t)it * 128;
#pragma unroll
        for (int j = 0; j < 4; ++j) {
            const uint32_t d = so + (rA ^ (j << 4));
            cp16(d, gA + ko + j * 16);
            cp16(d + A_BYTES, gB + ko + j * 16);
            cp16(d + A_BYTES + 16384, gB + ko + j * 16 + 1048576); // +128 rows
        }
    };

    // ---- ldsm base offsets (8 regs); k-step ks applies XOR (ks<<5) ----
    const int arow = wm * 64 + (lane & 15);
    const uint32_t acb = (lane & 16) >> 4;
    const int brow = wn * 64 + ((lane >> 4) << 3) + (lane & 7);
    const uint32_t bcb = (lane & 8) >> 3;
    uint32_t aoff0[4], boff0[4];
#pragma unroll
    for (int f = 0; f < 4; ++f) {
        aoff0[f] = swz(arow + f * 16, acb);              // (arow+16f)&7 const
        boff0[f] = A_BYTES + swz(brow + f * 16, bcb);
    }

    float acc[4][8][4];
#pragma unroll
    for (int i = 0; i < 4; ++i)
#pragma unroll
        for (int j = 0; j < 8; ++j)
#pragma unroll
            for (int k = 0; k < 4; ++k) acc[i][j][k] = 0.f;

    // ---- prologue ----
    load_stage(0, 0); cp_commit();
    load_stage(1, 1); cp_commit();
    cp_wait<1>();                 // stage 0 resident
    __syncthreads();

    uint32_t afr[2][4][4], bfr[2][4][4];
#pragma unroll
    for (int f = 0; f < 4; ++f) ldsm4(afr[0][f], sbase + aoff0[f]);
#pragma unroll
    for (int p = 0; p < 4; ++p) ldsm4(bfr[0][p], sbase + boff0[p]);

    int cur = 0;
    for (int i = 0; i < KITERS; ++i) {
        // issue stage i+2 into slot (i+2)%3 (stage i-1's slot; all warps
        // passed end-of-iter-(i-1) barrier after last read of it)
        if (i + 2 < KITERS) load_stage(i + 2, (i + 2) % NSTAGES);
        cp_commit();

        const uint32_t so = sbase + (uint32_t)(i % NSTAGES) * STAGE;
        // ks0..ks2: prefetch next k-step frags (XOR-derived addr), mma this one
#pragma unroll
        for (int ks = 0; ks < 3; ++ks) {
            const uint32_t kx = (uint32_t)(ks + 1) << 5;
#pragma unroll
            for (int f = 0; f < 4; ++f) ldsm4(afr[cur ^ 1][f], (so + aoff0[f]) ^ kx);
#pragma unroll
            for (int p = 0; p < 4; ++p) ldsm4(bfr[cur ^ 1][p], (so + boff0[p]) ^ kx);
#pragma unroll
            for (int f = 0; f < 4; ++f)
#pragma unroll
                for (int p = 0; p < 4; ++p) {
                    mma16816(acc[f][2 * p], afr[cur][f], bfr[cur][p][0], bfr[cur][p][1]);
                    mma16816(acc[f][2 * p + 1], afr[cur][f], bfr[cur][p][2], bfr[cur][p][3]);
                }
            cur ^= 1;
        }
        // ks3: mma only
#pragma unroll
        for (int f = 0; f < 4; ++f)
#pragma unroll
            for (int p = 0; p < 4; ++p) {
                mma16816(acc[f][2 * p], afr[cur][f], bfr[cur][p][0], bfr[cur][p][1]);
                mma16816(acc[f][2 * p + 1], afr[cur][f], bfr[cur][p][2], bfr[cur][p][3]);
            }

        // groups committed: s0..s(i+2); wait<1> -> s(i+1) resident
        cp_wait<1>();
        __syncthreads();

        // prefetch k0 frags of stage i+1
        if (i + 1 < KITERS) {
            const uint32_t sn = sbase + (uint32_t)((i + 1) % NSTAGES) * STAGE;
#pragma unroll
            for (int f = 0; f < 4; ++f) ldsm4(afr[cur ^ 1][f], sn + aoff0[f]);
#pragma unroll
            for (int p = 0; p < 4; ++p) ldsm4(bfr[cur ^ 1][p], sn + boff0[p]);
            cur ^= 1;
        }
    }

    // ---- epilogue: +bias, write float2 ----
    const int r0 = m0 + wm * 64 + (lane >> 2);
    const int c0 = n0 + wn * 64 + (lane & 3) * 2;
#pragma unroll
    for (int f = 0; f < 4; ++f) {
#pragma unroll
        for (int g = 0; g < 8; ++g) {
            int row = r0 + f * 16;
            int col = c0 + g * 8;
            float2 bz = *reinterpret_cast<const float2*>(bias + col);
            float2 o01, o23;
            o01.x = acc[f][g][0] + bz.x;
            o01.y = acc[f][g][1] + bz.y;
            o23.x = acc[f][g][2] + bz.x;
            o23.y = acc[f][g][3] + bz.y;
            *reinterpret_cast<float2*>(out + (size_t)row * Ndim + col) = o01;
            *reinterpret_cast<float2*>(out + (size_t)(row + 8) * Ndim + col) = o23;
        }
    }
}

// -------------------- host side --------------------------------------------
extern "C" void kernel_launch(void* const* d_in, const int* in_sizes, int n_in,
                              void* d_out, int out_size) {
    const float* x = (const float*)d_in[0];
    const float* w = (const float*)d_in[1];
    const float* bias = (const float*)d_in[2];
    float* out = (float*)d_out;

    void *p_xh = nullptr, *p_wh = nullptr;
    cudaGetSymbolAddress(&p_xh, g_xh);
    cudaGetSymbolAddress(&p_wh, g_wh);

    prep_fused<<<XBLK + WBLK, 256>>>((const float4*)x, (const float4*)w,
                                     (uint2*)p_xh, (uint2*)p_wh);

    static bool attr_set = false;
    if (!attr_set) {
        cudaFuncSetAttribute(gemm_f16,
                             cudaFuncAttributeMaxDynamicSharedMemorySize,
                             SMEM_TOTAL);
        attr_set = true;
    }

    dim3 grid(NTILES, MTILES);   // 2752 CTAs, rasterized in-kernel
    gemm_f16<<<grid, 256, SMEM_TOTAL>>>(
        (const unsigned char*)p_xh, (const unsigned char*)p_wh, bias, out);
}

// round 9
// speedup vs baseline: 2.6004x; 2.4765x over previous
#include <cuda_runtime.h>
#include <cuda_fp16.h>
#include <cstdint>

// ===========================================================================
// TernaryLinear: out[8192,11008] = x[8192,4096] @ sign(W)[11008,4096]^T + bias
//
// R9 = exact revert to the proven R4 GEMM structure (1712us, tensor 80.7%):
// fp16 x / fp16 sign(W), mma.sync.m16n8k16.f32, cp.async pipeline with BK=32,
// 80B-padded rows, sector-perfect loader (4 lanes x 64B contiguous per row),
// frag double-buffering, GROUP_M raster. Deltas vs R4: fused prep kernel and
// NSTAGES 6 -> 7 (same symbolic residency proof; smem 215040 < 227KB).
// The R5-8 BK=64/swizzle rewrite regressed 2.5x: its loader issued 32
// half-used 32B sectors per cp instr (L1 cycles x4.8) -- abandoned.
// ===========================================================================

#define DEVFN __device__ __forceinline__

static constexpr int Mdim = 8192, Ndim = 11008, Kdim = 4096;
static constexpr int BM = 128, BN = 256;
static constexpr int STRIDE = 80;                 // 64B K-chunk + 16B pad
static constexpr int NSTAGES = 7;
static constexpr int A_BYTES = BM * STRIDE;       // 10240
static constexpr int B_BYTES = BN * STRIDE;       // 20480
static constexpr int STAGE = A_BYTES + B_BYTES;   // 30720
static constexpr int SMEM_TOTAL = NSTAGES * STAGE;// 215040
static constexpr int KITERS = (Kdim * 2) / 64;    // 128 BK=32 chunks

static constexpr int MTILES = Mdim / BM;          // 64
static constexpr int NTILES = Ndim / BN;          // 43
static constexpr int GROUP_M = 16;

// -------------------- scratch (device globals; no cudaMalloc) --------------
__device__ __align__(128) unsigned char g_xh[(size_t)Mdim * Kdim * 2];
__device__ __align__(128) unsigned char g_wh[(size_t)Ndim * Kdim * 2];

// -------------------- PTX helpers ------------------------------------------
DEVFN uint32_t smem_u32(const void* p) {
    uint32_t a;
    asm("{ .reg .u64 t; cvta.to.shared.u64 t, %1; cvt.u32.u64 %0, t; }"
        : "=r"(a) : "l"(p));
    return a;
}
DEVFN void cp16(uint32_t dst, const void* src) {
    asm volatile("cp.async.cg.shared.global [%0], [%1], 16;"
                 :: "r"(dst), "l"(src) : "memory");
}
DEVFN void cp_commit() { asm volatile("cp.async.commit_group;" ::: "memory"); }
template <int N> DEVFN void cp_wait() {
    asm volatile("cp.async.wait_group %0;" :: "n"(N) : "memory");
}
DEVFN void ldsm4(uint32_t* r, uint32_t addr) {
    asm volatile("ldmatrix.sync.aligned.m8n8.x4.shared.b16 {%0,%1,%2,%3}, [%4];"
                 : "=r"(r[0]), "=r"(r[1]), "=r"(r[2]), "=r"(r[3]) : "r"(addr));
}
DEVFN void mma16816(float* d, const uint32_t* a, uint32_t b0, uint32_t b1) {
    asm volatile(
        "mma.sync.aligned.m16n8k16.row.col.f32.f16.f16.f32 "
        "{%0,%1,%2,%3}, {%4,%5,%6,%7}, {%8,%9}, {%0,%1,%2,%3};"
        : "+f"(d[0]), "+f"(d[1]), "+f"(d[2]), "+f"(d[3])
        : "r"(a[0]), "r"(a[1]), "r"(a[2]), "r"(a[3]), "r"(b0), "r"(b1));
}

// -------------------- fused preprocessing ----------------------------------
static constexpr int XBLK = (Mdim * Kdim / 4) / 256;   // 32768
static constexpr int WBLK = (Ndim * Kdim / 4) / 256;   // 44032

__global__ void prep_fused(const float4* __restrict__ x,
                           const float4* __restrict__ w,
                           uint2* __restrict__ xh, uint2* __restrict__ wh) {
    int b = blockIdx.x;
    if (b < XBLK) {
        int i = b * 256 + threadIdx.x;
        float4 v = x[i];
        __half2 h0 = __floats2half2_rn(v.x, v.y);
        __half2 h1 = __floats2half2_rn(v.z, v.w);
        uint2 u;
        u.x = *reinterpret_cast<uint32_t*>(&h0);
        u.y = *reinterpret_cast<uint32_t*>(&h1);
        xh[i] = u;
    } else {
        int i = (b - XBLK) * 256 + threadIdx.x;
        float4 v = w[i];
        float f[4] = {v.x, v.y, v.z, v.w};
        uint32_t s[4];
#pragma unroll
        for (int j = 0; j < 4; ++j)
            s[j] = f[j] > 0.f ? 0x3C00u : (f[j] < 0.f ? 0xBC00u : 0u);
        uint2 u;
        u.x = s[0] | (s[1] << 16);
        u.y = s[2] | (s[3] << 16);
        wh[i] = u;
    }
}

// -------------------- GEMM kernel ------------------------------------------
__global__ void __launch_bounds__(256, 1) gemm_f16(
    const unsigned char* __restrict__ A,   // fp16 [M][K]
    const unsigned char* __restrict__ B,   // fp16 [N][K]
    const float* __restrict__ bias,
    float* __restrict__ out)
{
    extern __shared__ __align__(128) unsigned char smem[];
    const uint32_t sbase = smem_u32(smem);
    const int tid = threadIdx.x;
    const int lane = tid & 31;
    const int wid = tid >> 5;
    const int wm = wid >> 2;        // 0..1
    const int wn = wid & 3;         // 0..3

    // ---- L2-friendly raster: bands of GROUP_M M-tiles sweeping N ----
    const int bid = blockIdx.y * gridDim.x + blockIdx.x;
    const int band = bid / (GROUP_M * NTILES);
    const int rem = bid % (GROUP_M * NTILES);
    const int m0 = (band * GROUP_M + (rem % GROUP_M)) * BM;
    const int n0 = (rem / GROUP_M) * BN;

    // ---- cp.async addressing: 4 lanes x 64B contiguous per row (sector-perfect)
    const int ar = tid >> 2;             // 0..63
    const int ac = (tid & 3) * 16;       // byte within 64B row chunk
    const size_t rowbytes = (size_t)Kdim * 2;   // 8192
    const unsigned char* gA = A + (size_t)(m0 + ar) * rowbytes + ac;
    const unsigned char* gB = B + (size_t)(n0 + ar) * rowbytes + ac;
    const uint32_t sA = sbase + ar * STRIDE + ac;
    const uint32_t sB = sbase + A_BYTES + ar * STRIDE + ac;

    // ---- ldmatrix per-lane addresses ----
    uint32_t aAddr[4], bAddr[4];
    {
        int arow = wm * 64 + (lane & 15);
        int acol = (lane & 16);
        int brow = wn * 64 + ((lane >> 4) << 3) + (lane & 7);
        int bcol = (lane & 8) << 1;
#pragma unroll
        for (int f = 0; f < 4; ++f) {
            aAddr[f] = sbase + (arow + f * 16) * STRIDE + acol;
            bAddr[f] = sbase + A_BYTES + (brow + f * 16) * STRIDE + bcol;
        }
    }

    float acc[4][8][4];
#pragma unroll
    for (int i = 0; i < 4; ++i)
#pragma unroll
        for (int j = 0; j < 8; ++j)
#pragma unroll
            for (int k = 0; k < 4; ++k) acc[i][j][k] = 0.f;

    auto load_stage = [&](int it, int s) {
        const uint32_t so = (uint32_t)s * STAGE;
        const size_t ko = (size_t)it * 64;
        cp16(sA + so, gA + ko);
        cp16(sA + so + 64 * STRIDE, gA + ko + 64 * rowbytes);
#pragma unroll
        for (int j = 0; j < 4; ++j)
            cp16(sB + so + j * 64 * STRIDE, gB + ko + (size_t)j * 64 * rowbytes);
    };

    // ---- prologue: issue NSTAGES-1 stages, wait until stages 0,1 resident --
#pragma unroll
    for (int s = 0; s < NSTAGES - 1; ++s) {
        load_stage(s, s);
        cp_commit();
    }
    cp_wait<NSTAGES - 3>();       // stages 0,1 resident
    __syncthreads();

    // frag double buffers
    uint32_t afr[2][4][4], bfr[2][4][4];
#pragma unroll
    for (int f = 0; f < 4; ++f) ldsm4(afr[0][f], aAddr[f]);
#pragma unroll
    for (int p = 0; p < 4; ++p) ldsm4(bfr[0][p], bAddr[p]);

    int cur = 0;
    for (int i = 0; i < KITERS; ++i) {
        const uint32_t soff = (uint32_t)(i % NSTAGES) * STAGE;
        const uint32_t noff = (uint32_t)((i + 1) % NSTAGES) * STAGE;

        // ks0: prefetch ks1 frags, mma on ks0 frags
#pragma unroll
        for (int f = 0; f < 4; ++f) ldsm4(afr[cur ^ 1][f], aAddr[f] + soff + 32);
#pragma unroll
        for (int p = 0; p < 4; ++p) ldsm4(bfr[cur ^ 1][p], bAddr[p] + soff + 32);
#pragma unroll
        for (int f = 0; f < 4; ++f)
#pragma unroll
            for (int p = 0; p < 4; ++p) {
                mma16816(acc[f][2 * p], afr[cur][f], bfr[cur][p][0], bfr[cur][p][1]);
                mma16816(acc[f][2 * p + 1], afr[cur][f], bfr[cur][p][2], bfr[cur][p][3]);
            }
        cur ^= 1;

        // ks1: prefetch next-stage ks0 frags, mma on ks1 frags
#pragma unroll
        for (int f = 0; f < 4; ++f) ldsm4(afr[cur ^ 1][f], aAddr[f] + noff);
#pragma unroll
        for (int p = 0; p < 4; ++p) ldsm4(bfr[cur ^ 1][p], bAddr[p] + noff);
#pragma unroll
        for (int f = 0; f < 4; ++f)
#pragma unroll
            for (int p = 0; p < 4; ++p) {
                mma16816(acc[f][2 * p], afr[cur][f], bfr[cur][p][0], bfr[cur][p][1]);
                mma16816(acc[f][2 * p + 1], afr[cur][f], bfr[cur][p][2], bfr[cur][p][3]);
            }
        cur ^= 1;

        // pipeline control. wait<NSTAGES-4>: after (NSTAGES-1)+i commits,
        // forces i+3 groups complete -> stages 0..i+2 resident -> iter i+1's
        // noff (stage i+2) frag prefetch is safe.
        cp_wait<NSTAGES - 4>();
        __syncthreads();
        if (i + NSTAGES - 1 < KITERS) load_stage(i + NSTAGES - 1, (i + NSTAGES - 1) % NSTAGES);
        cp_commit();
    }

    // ---- epilogue: +bias, write float2 ----
    const int r0 = m0 + wm * 64 + (lane >> 2);
    const int c0 = n0 + wn * 64 + (lane & 3) * 2;
#pragma unroll
    for (int f = 0; f < 4; ++f) {
#pragma unroll
        for (int g = 0; g < 8; ++g) {
            int row = r0 + f * 16;
            int col = c0 + g * 8;
            float2 bz = *reinterpret_cast<const float2*>(bias + col);
            float2 o01, o23;
            o01.x = acc[f][g][0] + bz.x;
            o01.y = acc[f][g][1] + bz.y;
            o23.x = acc[f][g][2] + bz.x;
            o23.y = acc[f][g][3] + bz.y;
            *reinterpret_cast<float2*>(out + (size_t)row * Ndim + col) = o01;
            *reinterpret_cast<float2*>(out + (size_t)(row + 8) * Ndim + col) = o23;
        }
    }
}

// -------------------- host side --------------------------------------------
extern "C" void kernel_launch(void* const* d_in, const int* in_sizes, int n_in,
                              void* d_out, int out_size) {
    const float* x = (const float*)d_in[0];
    const float* w = (const float*)d_in[1];
    const float* bias = (const float*)d_in[2];
    float* out = (float*)d_out;

    void *p_xh = nullptr, *p_wh = nullptr;
    cudaGetSymbolAddress(&p_xh, g_xh);
    cudaGetSymbolAddress(&p_wh, g_wh);

    prep_fused<<<XBLK + WBLK, 256>>>((const float4*)x, (const float4*)w,
                                     (uint2*)p_xh, (uint2*)p_wh);

    static bool attr_set = false;
    if (!attr_set) {
        cudaFuncSetAttribute(gemm_f16,
                             cudaFuncAttributeMaxDynamicSharedMemorySize,
                             SMEM_TOTAL);
        attr_set = true;
    }

    dim3 grid(NTILES, MTILES);   // 2752 CTAs, rasterized in-kernel
    gemm_f16<<<grid, 256, SMEM_TOTAL>>>(
        (const unsigned char*)p_xh, (const unsigned char*)p_wh, bias, out);
}